// round 11
// baseline (speedup 1.0000x reference)
#include <cuda_runtime.h>

#define BLOCK   128
#define WPB     4
#define NSM     152
#define OCC     8
#define NBLOCKS (NSM * OCC)          // 1216
#define NWARPS  (NBLOCKS * WPB)      // 4864 chunks, 1 per warp
#define WARM    8
#define PSP     36

typedef unsigned long long u64;

__device__ __forceinline__ u64 pk2(float a, float b) {
    u64 r; asm("mov.b64 %0, {%1,%2};" : "=l"(r) : "f"(a), "f"(b)); return r;
}
__device__ __forceinline__ void unpk2(float& a, float& b, u64 r) {
    asm("mov.b64 {%0,%1}, %2;" : "=f"(a), "=f"(b) : "l"(r));
}
__device__ __forceinline__ u64 fma2(u64 a, u64 b, u64 c) {
    u64 d; asm("fma.rn.f32x2 %0, %1, %2, %3;" : "=l"(d) : "l"(a), "l"(b), "l"(c)); return d;
}
__device__ __forceinline__ float ftanh(float x) {
    float r; asm("tanh.approx.f32 %0, %1;" : "=f"(r) : "f"(x)); return r;
}
__device__ __forceinline__ void cpa16(unsigned d, const void* s) {
    asm volatile("cp.async.ca.shared.global [%0], [%1], 16;" :: "r"(d), "l"(s));
}
__device__ __forceinline__ void cpacommit() { asm volatile("cp.async.commit_group;"); }
__device__ __forceinline__ void cpawait0()  { asm volatile("cp.async.wait_group 0;"); }

__global__ void __launch_bounds__(BLOCK, OCC) rnn_scan_kernel(
    const float* __restrict__ x, const float* __restrict__ weight,
    const float* __restrict__ weight_y, const float* __restrict__ bias,
    const float* __restrict__ weight_ln, const float* __restrict__ bias_ln,
    float* __restrict__ out, int B, int L)
{
    __shared__ __align__(16) float xs[WPB][2][16][16];    // x tiles, double-buffered
    __shared__ __align__(16) float ps[WPB][2][16][PSP];   // partials, double-buffered

    const int w    = threadIdx.x >> 5;
    const int lane = threadIdx.x & 31;
    const int wid  = blockIdx.x * WPB + w;
    const int start = wid * L;
    if (start >= B) return;
    const int tstop = min(start + L, B);
    const int t0    = max(0, start - WARM);   // contraction warmup (<=0.25^8)
    const int nt    = (tstop - t0 + 15) >> 4;

    // sigma(y) = 0.5 + 0.5*tanh(y/2); z = y/2; state t = tanh(z):
    //   z = (0.5*bias + 0.25*wy_h) + x·(0.5 W) + (0.25*wy_h)*t
    const float SC = 0.5f;

    // Lane owns hidden (h0,h1)=(2l,2l+1); crossed-half chains: x multiplier is
    // the natural pair {x_2k,x_2k+1}: z[h0]=c0.lo+c1.hi, z[h1]=c1.lo+c0.hi.
    const int h0 = 2 * lane, h1 = 2 * lane + 1;
    u64 w0k[8], w1k[8];
#pragma unroll
    for (int k = 0; k < 8; k++) {
        const float* r0 = weight + (2 * k) * 64;
        const float* r1 = weight + (2 * k + 1) * 64;
        w0k[k] = pk2(SC * r0[h0], SC * r1[h1]);
        w1k[k] = pk2(SC * r0[h1], SC * r1[h0]);
    }
    const float wyt0 = 0.25f * weight_y[h0];
    const float wyt1 = 0.25f * weight_y[h1];
    const float hl0  = 0.5f * weight_ln[h0];
    const float hl1  = 0.5f * weight_ln[h1];
    const float hsum = hl0 + hl1;
    const float bln  = bias_ln[0];
    const u64 binit0 = pk2(SC * bias[0] + wyt0, 0.f);
    const u64 binit1 = pk2(SC * bias[0] + wyt1, 0.f);

    float t0s = -1.f, t1s = -1.f;    // t = 2s-1; s_init = 0 -> t = -1
    float zE0 = 0.f, zE1 = 0.f;      // final-carry z; written only in last tile

    auto issue = [&](int tb, int st) {
#pragma unroll
        for (int r = 0; r < 2; r++) {
            int slot = lane + r * 32;
            int row = slot >> 2, q = slot & 3;
            int t = min(tb + row, B - 1);
            cpa16((unsigned)__cvta_generic_to_shared(&xs[w][st][row][q * 4]),
                  x + (size_t)t * 64 + q * 4);
        }
    };

    auto matvecR = [&](const float* xrow, float& m0, float& m1) {
        const ulonglong2* xr = (const ulonglong2*)(xrow);
        ulonglong2 qa = xr[0], qb = xr[1], qc = xr[2], qd = xr[3];
        u64 c0 = binit0, c1 = binit1;
        c0 = fma2(qa.x, w0k[0], c0);  c1 = fma2(qa.x, w1k[0], c1);
        c0 = fma2(qa.y, w0k[1], c0);  c1 = fma2(qa.y, w1k[1], c1);
        c0 = fma2(qb.x, w0k[2], c0);  c1 = fma2(qb.x, w1k[2], c1);
        c0 = fma2(qb.y, w0k[3], c0);  c1 = fma2(qb.y, w1k[3], c1);
        c0 = fma2(qc.x, w0k[4], c0);  c1 = fma2(qc.x, w1k[4], c1);
        c0 = fma2(qc.y, w0k[5], c0);  c1 = fma2(qc.y, w1k[5], c1);
        c0 = fma2(qd.x, w0k[6], c0);  c1 = fma2(qd.x, w1k[6], c1);
        c0 = fma2(qd.y, w0k[7], c0);  c1 = fma2(qd.y, w1k[7], c1);
        float a0, b0, a1, b1;
        unpk2(a0, b0, c0);
        unpk2(a1, b1, c1);
        m0 = a0 + b1;
        m1 = a1 + b0;
    };

    // hot-path recur: t-update + partial store only (no z kept live)
    auto recur = [&](float m0, float m1, int st, int j) {
        t0s = ftanh(fmaf(wyt0, t0s, m0));
        t1s = ftanh(fmaf(wyt1, t1s, m1));
        ps[w][st][j][lane] = fmaf(hl1, t1s, fmaf(hl0, t0s, hsum));
    };

    const int jj   = lane & 15;
    const int half = lane >> 4;

    auto reducePS = [&](int st_, int tb_) {
        const float4* pr = (const float4*)(&ps[w][st_][jj][half * 16]);
        float4 a0 = pr[0], a1 = pr[1], a2 = pr[2], a3 = pr[3];
        float r0 = ((a0.x + a0.y) + (a0.z + a0.w)) + ((a1.x + a1.y) + (a1.z + a1.w));
        float r1 = ((a2.x + a2.y) + (a2.z + a2.w)) + ((a3.x + a3.y) + (a3.z + a3.w));
        float r = r0 + r1;
        r += __shfl_xor_sync(0xffffffffu, r, 16);
        int t = tb_ + jj;
        if (half == 0 && t >= start && t < tstop)
            out[t] = bln + r;
    };

    // Prologue: tile 0 in smem; establish invariant m = matvec(step t0)
    issue(t0, 0);
    cpacommit();
    cpawait0();
    __syncwarp();

    float m0, m1;
    matvecR(xs[w][0][0], m0, m1);

    int tb = t0;

    for (int k = 0; k < nt; k++) {
        const int st = k & 1;
        const bool notLast = (k + 1 < nt);
        if (notLast) { issue(tb + 16, st ^ 1); cpacommit(); }

        const float (*xa)[16] = xs[w][st];

        if (notLast) {
            // non-last tiles are always full (16 steps); rotated pipeline:
            // recur consumes m (step tb+j), then matvec computes m for step tb+j+1
#pragma unroll
            for (int j = 0; j < 16; j++) {
                recur(m0, m1, st, j);
                if (j < 15) matvecR(xa[j + 1], m0, m1);
            }
        } else {
            // final tile (possibly partial): maintains z for the final carry
            const int n = tstop - tb;
            for (int j = 0; j < n; j++) {
                zE0 = fmaf(wyt0, t0s, m0);
                zE1 = fmaf(wyt1, t1s, m1);
                t0s = ftanh(zE0);
                t1s = ftanh(zE1);
                ps[w][st][j][lane] = fmaf(hl1, t1s, fmaf(hl0, t0s, hsum));
                if (j + 1 < n) matvecR(xa[j + 1], m0, m1);
            }
        }
        __syncwarp();

        reducePS(st, tb);   // outputs of this tile (guarded by [start, tstop))
        // next tile writes ps stage st^1: no sync needed (double-buffered)

        if (notLast) {
            cpawait0();
            __syncwarp();
            matvecR(xs[w][st ^ 1][0], m0, m1);   // re-establish invariant
        }
        tb += 16;
    }

    // Unique last chunk writes final carries: y_h = 2z, y_hs = 0.5 + 0.5*t
    if (start + L >= B) {
        *(float2*)(out + B + 2 * lane) = make_float2(2.f * zE0, 2.f * zE1);
        *(float2*)(out + B + 64 + 2 * lane) =
            make_float2(fmaf(0.5f, t0s, 0.5f), fmaf(0.5f, t1s, 0.5f));
    }
}

extern "C" void kernel_launch(void* const* d_in, const int* in_sizes, int n_in,
                              void* d_out, int out_size)
{
    const float* x   = (const float*)d_in[0];
    const float* wt  = (const float*)d_in[1];
    const float* wy  = (const float*)d_in[2];
    const float* b   = (const float*)d_in[3];
    const float* wln = (const float*)d_in[4];
    const float* bln = (const float*)d_in[5];
    float* out = (float*)d_out;

    const int B = in_sizes[0] / 64;              // x is (B, T=4, I=16); row stride 64
    const int L = (B + NWARPS - 1) / NWARPS;     // steps per chunk

    rnn_scan_kernel<<<NBLOCKS, BLOCK>>>(x, wt, wy, b, wln, bln, out, B, L);
}

// round 12
// speedup vs baseline: 1.1024x; 1.1024x over previous
#include <cuda_runtime.h>

#define BLOCK   128
#define WPB     4
#define NSM     152
#define OCC     7
#define NBLOCKS (NSM * OCC)          // 1064
#define NWARPS  (NBLOCKS * WPB)      // 4256 chunks, 1 per warp
#define WARM    8
#define PSP     36

typedef unsigned long long u64;

__device__ __forceinline__ u64 pk2(float a, float b) {
    u64 r; asm("mov.b64 %0, {%1,%2};" : "=l"(r) : "f"(a), "f"(b)); return r;
}
__device__ __forceinline__ void unpk2(float& a, float& b, u64 r) {
    asm("mov.b64 {%0,%1}, %2;" : "=f"(a), "=f"(b) : "l"(r));
}
__device__ __forceinline__ u64 fma2(u64 a, u64 b, u64 c) {
    u64 d; asm("fma.rn.f32x2 %0, %1, %2, %3;" : "=l"(d) : "l"(a), "l"(b), "l"(c)); return d;
}
__device__ __forceinline__ float ftanh(float x) {
    float r; asm("tanh.approx.f32 %0, %1;" : "=f"(r) : "f"(x)); return r;
}
__device__ __forceinline__ void cpa16(unsigned d, const void* s) {
    asm volatile("cp.async.ca.shared.global [%0], [%1], 16;" :: "r"(d), "l"(s));
}
__device__ __forceinline__ void cpacommit() { asm volatile("cp.async.commit_group;"); }
__device__ __forceinline__ void cpawait0()  { asm volatile("cp.async.wait_group 0;"); }

__global__ void __launch_bounds__(BLOCK, OCC) rnn_scan_kernel(
    const float* __restrict__ x, const float* __restrict__ weight,
    const float* __restrict__ weight_y, const float* __restrict__ bias,
    const float* __restrict__ weight_ln, const float* __restrict__ bias_ln,
    float* __restrict__ out, int B, int L)
{
    __shared__ __align__(16) float xs[WPB][2][16][16];    // x tiles, double-buffered
    __shared__ __align__(16) float ps[WPB][2][16][PSP];   // partials, double-buffered

    const int w    = threadIdx.x >> 5;
    const int lane = threadIdx.x & 31;
    const int wid  = blockIdx.x * WPB + w;
    const int start = wid * L;
    if (start >= B) return;
    const int tstop = min(start + L, B);
    const int t0    = max(0, start - WARM);   // contraction warmup (<=0.25^8)
    const int nt    = (tstop - t0 + 15) >> 4;

    // sigma(y) = 0.5 + 0.5*tanh(y/2); z = y/2; state t = tanh(z):
    //   z = (0.5*bias + 0.25*wy_h) + x·(0.5 W) + (0.25*wy_h)*t
    const float SC = 0.5f;

    // Lane owns hidden (h0,h1)=(2l,2l+1); crossed-half chains: x multiplier is
    // the natural pair {x_2k,x_2k+1}: z[h0]=c0.lo+c1.hi, z[h1]=c1.lo+c0.hi.
    const int h0 = 2 * lane, h1 = 2 * lane + 1;
    u64 w0k[8], w1k[8];
#pragma unroll
    for (int k = 0; k < 8; k++) {
        const float* r0 = weight + (2 * k) * 64;
        const float* r1 = weight + (2 * k + 1) * 64;
        w0k[k] = pk2(SC * r0[h0], SC * r1[h1]);
        w1k[k] = pk2(SC * r0[h1], SC * r1[h0]);
    }
    const float wyt0 = 0.25f * weight_y[h0];
    const float wyt1 = 0.25f * weight_y[h1];
    const float hl0  = 0.5f * weight_ln[h0];
    const float hl1  = 0.5f * weight_ln[h1];
    const float hsum = hl0 + hl1;
    const float bln  = bias_ln[0];
    const u64 binit0 = pk2(SC * bias[0] + wyt0, 0.f);
    const u64 binit1 = pk2(SC * bias[0] + wyt1, 0.f);

    float z0 = 0.f, z1 = 0.f;
    float t0s = -1.f, t1s = -1.f;    // t = 2s-1; s_init = 0 -> t = -1

    // Hoisted cp.async addressing: lane covers rows {lrow, lrow+8}, 16B col lq4
    const int lrow = lane >> 2;
    const int lq4  = (lane & 3) * 4;
    unsigned sdst[2][2];
#pragma unroll
    for (int st = 0; st < 2; st++) {
        sdst[st][0] = (unsigned)__cvta_generic_to_shared(&xs[w][st][lrow][lq4]);
        sdst[st][1] = (unsigned)__cvta_generic_to_shared(&xs[w][st][8 + lrow][lq4]);
    }
    const float* xlane = x + (size_t)lrow * 64 + lq4;

    auto issue = [&](int tb, int st) {
        int ta = min(tb, B - 1 - lrow);          // clamp keeps reads in-bounds
        int tb2 = min(tb + 8, B - 1 - lrow);
        cpa16(sdst[st][0], xlane + (size_t)ta * 64);
        cpa16(sdst[st][1], xlane + (size_t)tb2 * 64);
    };

    auto matvecR = [&](const float* xrow, float& m0, float& m1) {
        const ulonglong2* xr = (const ulonglong2*)(xrow);
        ulonglong2 qa = xr[0], qb = xr[1], qc = xr[2], qd = xr[3];
        u64 c0 = binit0, c1 = binit1;
        c0 = fma2(qa.x, w0k[0], c0);  c1 = fma2(qa.x, w1k[0], c1);
        c0 = fma2(qa.y, w0k[1], c0);  c1 = fma2(qa.y, w1k[1], c1);
        c0 = fma2(qb.x, w0k[2], c0);  c1 = fma2(qb.x, w1k[2], c1);
        c0 = fma2(qb.y, w0k[3], c0);  c1 = fma2(qb.y, w1k[3], c1);
        c0 = fma2(qc.x, w0k[4], c0);  c1 = fma2(qc.x, w1k[4], c1);
        c0 = fma2(qc.y, w0k[5], c0);  c1 = fma2(qc.y, w1k[5], c1);
        c0 = fma2(qd.x, w0k[6], c0);  c1 = fma2(qd.x, w1k[6], c1);
        c0 = fma2(qd.y, w0k[7], c0);  c1 = fma2(qd.y, w1k[7], c1);
        float a0, b0, a1, b1;
        unpk2(a0, b0, c0);
        unpk2(a1, b1, c1);
        m0 = a0 + b1;
        m1 = a1 + b0;
    };

    // the only serial part (2 FFMA + 2 TANH + partial store)
    auto recur = [&](float m0, float m1, int st, int j) {
        z0 = fmaf(wyt0, t0s, m0);
        z1 = fmaf(wyt1, t1s, m1);
        t0s = ftanh(z0);
        t1s = ftanh(z1);
        ps[w][st][j][lane] = fmaf(hl1, t1s, fmaf(hl0, t0s, hsum));
    };

    // Prologue: tile 0 in smem
    issue(t0, 0);
    cpacommit();
    cpawait0();
    __syncwarp();

    // Pipeline invariant entering each full tile: m = matvec(row 0 of tile)
    float m0, m1;
    matvecR(xs[w][0][0], m0, m1);

    int tb = t0;
    const int jj   = lane & 15;
    const int half = lane >> 4;

    for (int k = 0; k < nt; k++) {
        const int st = k & 1;
        if (k + 1 < nt) { issue(tb + 16, st ^ 1); cpacommit(); }

        const int n = min(16, tstop - tb);
        const float (*xa)[16] = xs[w][st];

        if (n == 16) {
            // Two-step rotation: matvec(j+1) BEFORE recur(j) (r7 interleave),
            // m/n roles alternate so no register copies are needed.
            float n0, n1;
#pragma unroll
            for (int jp = 0; jp < 8; jp++) {
                const int j = 2 * jp;
                matvecR(xa[j + 1], n0, n1);     // step j+1's matvec
                recur(m0, m1, st, j);           // step j (independent of it)
                if (jp < 7) {
                    matvecR(xa[j + 2], m0, m1); // step j+2's matvec
                    recur(n0, n1, st, j + 1);   // step j+1
                } else {
                    recur(n0, n1, st, 15);      // step 15; m re-established below
                }
            }
        } else {
            // edge tile (last, partial): simple non-pipelined path
            for (int j = 0; j < n; j++) {
                const ulonglong2* rr = (const ulonglong2*)(&xa[j][0]);
                float e0, e1;
                matvecR((const float*)rr, e0, e1);
                recur(e0, e1, st, j);
            }
        }
        __syncwarp();

        // Reduce: lane (half, jj) sums 16 partials of step tb+jj; combine halves
        {
            const float4* pr = (const float4*)(&ps[w][st][jj][half * 16]);
            float4 a0 = pr[0], a1 = pr[1], a2 = pr[2], a3 = pr[3];
            float r0 = ((a0.x + a0.y) + (a0.z + a0.w)) + ((a1.x + a1.y) + (a1.z + a1.w));
            float r1 = ((a2.x + a2.y) + (a2.z + a2.w)) + ((a3.x + a3.y) + (a3.z + a3.w));
            float r = r0 + r1;
            r += __shfl_xor_sync(0xffffffffu, r, 16);
            int t = tb + jj;
            if (half == 0 && t >= start && t < tstop)
                out[t] = bln + r;
        }
        // next tile writes ps stage st^1: no sync needed (double-buffered)

        if (k + 1 < nt) {
            cpawait0();
            __syncwarp();
            matvecR(xs[w][st ^ 1][0], m0, m1);   // re-establish pipeline invariant
        }
        tb += 16;
    }

    // Unique last chunk writes final carries: y_h = 2z, y_hs = 0.5 + 0.5*t
    if (start + L >= B) {
        *(float2*)(out + B + 2 * lane) = make_float2(2.f * z0, 2.f * z1);
        *(float2*)(out + B + 64 + 2 * lane) =
            make_float2(fmaf(0.5f, t0s, 0.5f), fmaf(0.5f, t1s, 0.5f));
    }
}

extern "C" void kernel_launch(void* const* d_in, const int* in_sizes, int n_in,
                              void* d_out, int out_size)
{
    const float* x   = (const float*)d_in[0];
    const float* wt  = (const float*)d_in[1];
    const float* wy  = (const float*)d_in[2];
    const float* b   = (const float*)d_in[3];
    const float* wln = (const float*)d_in[4];
    const float* bln = (const float*)d_in[5];
    float* out = (float*)d_out;

    const int B = in_sizes[0] / 64;              // x is (B, T=4, I=16); row stride 64
    const int L = (B + NWARPS - 1) / NWARPS;     // steps per chunk

    rnn_scan_kernel<<<NBLOCKS, BLOCK>>>(x, wt, wy, b, wln, bln, out, B, L);
}